// round 13
// baseline (speedup 1.0000x reference)
#include <cuda_runtime.h>
#include <cuda_fp16.h>
#include <cstdint>

// Correlation layer via band-restricted mma.sync (m16n8k16 fp16, fp32 accum).
// out[b, di*9+dj, h, w] = sum_c f1[b,c,h,w] * f2[b,c,h+di-4,w+dj-4]
// B=8, C=256, H=64, W=128, D=81.
//
// R13 = R7 compute core (8 m16 warps, acc[9][3][4], ldsm2t x3 band, NBUF=4)
//     + padded-gmem f2 pre-cast (16B division-free cp.async, no smem zeroing)
//     + in-kernel f1 cast ring (LDG.128 fp32 x2 -> pack -> STS.128 fp16),
//       so the standalone cast pass handles f2 only.

#define NB 8
#define NC 256
#define NH 64
#define NW 128
#define ND 81
#define PW 136                       // padded f2 row (halves); data at cols [4,132)

#define RSTRIDE 272                  // smem c-row bytes; %128==16 -> LDSM conflict-free
#define F2ROW (16 * RSTRIDE)         // 4352 B per r per 16-c chunk
#define F2CHUNK (9 * F2ROW)          // 39168 B: all 9 r rows of one chunk
#define NBUF 4
#define OFF_F1 (NBUF * F2CHUNK)      // 156672
#define F1SLOT F2ROW                 // 4352 B per f1 chunk slot (16c x 128w fp16, stride 272)
#define SMEM_SZ (OFF_F1 + 4 * F1SLOT)   // 174080 B -> 1 CTA/SM
#define STAGE_W 25                   // floats per epilogue staging row

__device__ __half g_f2h[(size_t)NB * NC * NH * PW];

// ---------------- fp32 -> padded fp16 cast for f2 ----------------
__global__ void cast_kernel(const float* __restrict__ f2) {
    int idx = blockIdx.x * 256 + threadIdx.x;   // one 16B output seg
    int row = idx / 17, sg = idx % 17;          // row = ((b*NC+c)*NH+h)
    const float* src = f2 + (size_t)row * NW;
    __half hv[8];
    #pragma unroll
    for (int k = 0; k < 8; k++) {
        int col = 8 * sg - 4 + k;
        float v = (col >= 0 && col < NW) ? src[col] : 0.0f;
        hv[k] = __float2half_rn(v);
    }
    *reinterpret_cast<uint4*>(g_f2h + (size_t)row * PW + 8 * sg) =
        *reinterpret_cast<const uint4*>(hv);
}

// ---------------- PTX helpers ----------------
__device__ __forceinline__ void cpa16(uint32_t dst, const void* src) {
    asm volatile("cp.async.ca.shared.global [%0], [%1], 16;" :: "r"(dst), "l"(src));
}
__device__ __forceinline__ void ldsm4t(uint32_t& r0, uint32_t& r1,
                                       uint32_t& r2, uint32_t& r3, uint32_t a) {
    asm volatile("ldmatrix.sync.aligned.m8n8.x4.trans.shared.b16 {%0,%1,%2,%3}, [%4];"
                 : "=r"(r0), "=r"(r1), "=r"(r2), "=r"(r3) : "r"(a));
}
__device__ __forceinline__ void ldsm2t(uint32_t& r0, uint32_t& r1, uint32_t a) {
    asm volatile("ldmatrix.sync.aligned.m8n8.x2.trans.shared.b16 {%0,%1}, [%2];"
                 : "=r"(r0), "=r"(r1) : "r"(a));
}
__device__ __forceinline__ void mma16816(float* d, uint32_t a0, uint32_t a1,
                                         uint32_t a2, uint32_t a3,
                                         uint32_t b0, uint32_t b1) {
    asm volatile("mma.sync.aligned.m16n8k16.row.col.f32.f16.f16.f32 "
                 "{%0,%1,%2,%3}, {%4,%5,%6,%7}, {%8,%9}, {%0,%1,%2,%3};"
                 : "+f"(d[0]), "+f"(d[1]), "+f"(d[2]), "+f"(d[3])
                 : "r"(a0), "r"(a1), "r"(a2), "r"(a3), "r"(b0), "r"(b1));
}
__device__ __forceinline__ uint32_t pkh2(float lo, float hi) {
    __half2 h = __floats2half2_rn(lo, hi);
    return *reinterpret_cast<uint32_t*>(&h);
}

// ---------------- main kernel ----------------
__global__ void __launch_bounds__(256, 1)
corr_mma(const float* __restrict__ f1, float* __restrict__ out) {
    extern __shared__ char smem[];
    const uint32_t sb = (uint32_t)__cvta_generic_to_shared(smem);
    const int tid = threadIdx.x;
    const int lane = tid & 31, m = tid >> 5;    // warp = m16 w-block
    const int h = blockIdx.x, b = blockIdx.y;

    float acc[9][3][4];
    #pragma unroll
    for (int r = 0; r < 9; r++)
        #pragma unroll
        for (int t = 0; t < 3; t++)
            #pragma unroll
            for (int k = 0; k < 4; k++)
                acc[r][t][k] = 0.0f;

    // A (f1 fp16 slot, [c][w], .trans x4): quads (m0-7,k0-7),(m8-15,k0-7),
    // (m0-7,k8-15),(m8-15,k8-15).
    const int q = lane >> 3, lrow = lane & 7;
    const uint32_t a_off = (uint32_t)(lrow + ((q >> 1) << 3)) * RSTRIDE
                         + ((16 * m + ((q & 1) << 3)) << 1);
    // B (f2 fp16, [c][w'], .trans x2): rows c = lane%16.
    const uint32_t b_row_off = (uint32_t)(lane & 15) * RSTRIDE;

    // Division-free f2 loader: thread (ci, sg) copies seg sg of each r's row;
    // sg==0 threads also copy seg 16 (272B row = 17 segs).
    const int ci = tid >> 4, sg = tid & 15;
    auto issue = [&](int cc) {
        const int c0 = cc * 16;
        const uint32_t dbase = sb + (cc & (NBUF - 1)) * F2CHUNK;
        #pragma unroll
        for (int r = 0; r < 9; r++) {
            int gr = h + r - 4;
            gr = gr < 0 ? 0 : (gr > NH - 1 ? NH - 1 : gr);  // clamp; invalid di never stored
            const __half* rowp = g_f2h + ((size_t)(b * NC + c0 + ci) * NH + gr) * PW;
            const uint32_t d = dbase + r * F2ROW + ci * RSTRIDE;
            cpa16(d + 16 * sg, rowp + 8 * sg);
            if (sg == 0) cpa16(d + 256, rowp + 128);
        }
    };

    // f1 in-kernel cast: LDG fp32 (2x float4) for chunk cc into regs,
    // then pack+STS.128 into the 4-slot fp16 ring.
    const float* f1base = f1 + ((size_t)b * NC + ci) * (NH * NW) + h * NW + 8 * sg;
    float4 v0, v1;
    auto ldf1 = [&](int cc) {
        const float* p = f1base + (size_t)cc * 16 * (NH * NW);
        v0 = __ldg((const float4*)p);
        v1 = __ldg((const float4*)(p + 4));
    };
    auto stf1 = [&](int cc) {
        uint4 pk;
        pk.x = pkh2(v0.x, v0.y); pk.y = pkh2(v0.z, v0.w);
        pk.z = pkh2(v1.x, v1.y); pk.w = pkh2(v1.z, v1.w);
        uint32_t d = sb + OFF_F1 + (cc & 3) * F1SLOT + ci * RSTRIDE + 16 * sg;
        asm volatile("st.shared.v4.b32 [%0], {%1,%2,%3,%4};"
                     :: "r"(d), "r"(pk.x), "r"(pk.y), "r"(pk.z), "r"(pk.w) : "memory");
    };

    // prologue
    ldf1(0);
    issue(0); asm volatile("cp.async.commit_group;");
    issue(1); asm volatile("cp.async.commit_group;");
    issue(2); asm volatile("cp.async.commit_group;");
    stf1(0);
    ldf1(1);

    for (int cc = 0; cc < 16; cc++) {
        asm volatile("cp.async.wait_group 2;");   // f2 chunk cc complete
        __syncthreads();                          // publishes f2 buf cc and f1 slot cc
        if (cc + 3 < 16) issue(cc + 3);           // buf (cc+3)&3 == (cc-1)&3: consumed pre-barrier
        asm volatile("cp.async.commit_group;");   // empty at tail keeps count uniform
        if (cc + 1 < 16) stf1(cc + 1);            // regs from ldf1(cc+1); slot published next barrier
        if (cc + 2 < 16) ldf1(cc + 2);

        const uint32_t f1s = sb + OFF_F1 + (cc & 3) * F1SLOT;
        uint32_t a0, a1, a2, a3;
        ldsm4t(a0, a1, a2, a3, f1s + a_off);
        const uint32_t cbase = sb + (cc & (NBUF - 1)) * F2CHUNK;
        #pragma unroll
        for (int r = 0; r < 9; r++) {
            const uint32_t brow = cbase + r * F2ROW + b_row_off + 32 * m;
            #pragma unroll
            for (int t = 0; t < 3; t++) {
                uint32_t b0, b1;
                ldsm2t(b0, b1, brow + 16 * t);   // n8 tile at padded col 16m + 8t
                mma16816(acc[r][t], a0, a1, a2, a3, b0, b1);
            }
        }
    }

    // ---------------- epilogue: band extraction via per-warp staging ----------------
    __syncthreads();   // buffers dead; staging aliases them
    float* stage = reinterpret_cast<float*>(smem) + m * 16 * STAGE_W;
    const int gid = lane >> 2, tig = lane & 3;
    const int l16 = lane & 15, dh = lane >> 4;
    #pragma unroll
    for (int r = 0; r < 9; r++) {
        #pragma unroll
        for (int t = 0; t < 3; t++) {
            stage[gid * STAGE_W + 8 * t + 2 * tig]           = acc[r][t][0];
            stage[gid * STAGE_W + 8 * t + 2 * tig + 1]       = acc[r][t][1];
            stage[(gid + 8) * STAGE_W + 8 * t + 2 * tig]     = acc[r][t][2];
            stage[(gid + 8) * STAGE_W + 8 * t + 2 * tig + 1] = acc[r][t][3];
        }
        __syncwarp();
        const int gr = h + r - 4;
        const bool valid = (gr >= 0 && gr < NH);
        // out[b, r*9+dj, h, 16m+l16] = band[l16][l16+dj] (padded-col space;
        // out-of-range w+dj-4 hit gmem-baked zeros)
        #pragma unroll
        for (int rd = 0; rd < 5; rd++) {
            int dj = 2 * rd + dh;
            if (dj < 9) {
                float v = valid ? stage[l16 * STAGE_W + l16 + dj] : 0.0f;
                out[(((size_t)b * ND + r * 9 + dj) * NH + h) * NW + 16 * m + l16] = v;
            }
        }
        __syncwarp();
    }
}

extern "C" void kernel_launch(void* const* d_in, const int* in_sizes, int n_in,
                              void* d_out, int out_size) {
    const float* f1 = (const float*)d_in[0];
    const float* f2 = (const float*)d_in[1];
    float* out = (float*)d_out;

    cudaFuncSetAttribute(corr_mma, cudaFuncAttributeMaxDynamicSharedMemorySize, SMEM_SZ);

    // (NB*NC*NH rows) * 17 segs / 256 threads = 8704 blocks exactly
    cast_kernel<<<8704, 256>>>(f2);
    corr_mma<<<dim3(NH, NB), 256, SMEM_SZ>>>(f1, out);
}